// round 2
// baseline (speedup 1.0000x reference)
#include <cuda_runtime.h>
#include <math.h>
#include <stdint.h>

#define NB 8
#define NS 2048
#define NE 512
#define NH 8
#define ND 64

// ---- scratch (static device globals; no allocation) ----
__device__ float g_Q[(size_t)NB * NH * NS * ND];   // (b,h,s,d)
__device__ float g_K[(size_t)NB * NH * NS * ND];
__device__ float g_V[(size_t)NB * NH * NS * ND];
__device__ float g_att[(size_t)NB * NS * NE];      // (b*s, h*64+d)
__device__ float g_Y[(size_t)NB * NS * NE];

// ============================================================
// Fused SGEMM: 128x128x8 block tile, 8x8 per-thread microtile.
// mode 0: X=x_p,  W=Wq  (N=512)  -> scatter into g_Q (b,h,s,d)
// mode 1: X=x_pcre, W=Wkv (N=1024)-> scatter into g_K / g_V
// mode 2: X=g_att, W=Wff (N=512) -> + bff + resid -> g_Y
// ============================================================
__global__ __launch_bounds__(256) void sgemm_fused(
    const float* __restrict__ X, const float* __restrict__ W,
    const float* __restrict__ bff, const float* __restrict__ resid,
    int N, int mode)
{
    __shared__ float As[8][128];   // transposed A tile
    __shared__ float Bs[8][128];
    const int K = NE;
    const int tid = threadIdx.x;
    const int bn = blockIdx.x, bm = blockIdx.y;
    const int rowA = tid >> 1, colA = (tid & 1) << 2;
    const int rowB = tid >> 5, colB = (tid & 31) << 2;
    const int tr = tid >> 4, tc = tid & 15;

    const float* Xbase = (mode == 2) ? g_att : X;
    const float* Xp = Xbase + (size_t)bm * 128 * K;
    const float* Wp = W + (size_t)bn * 128;

    float acc[8][8];
#pragma unroll
    for (int i = 0; i < 8; i++)
#pragma unroll
        for (int j = 0; j < 8; j++) acc[i][j] = 0.f;

    for (int k0 = 0; k0 < K; k0 += 8) {
        float4 a = *(const float4*)(Xp + (size_t)rowA * K + k0 + colA);
        As[colA + 0][rowA] = a.x;
        As[colA + 1][rowA] = a.y;
        As[colA + 2][rowA] = a.z;
        As[colA + 3][rowA] = a.w;
        *(float4*)&Bs[rowB][colB] =
            *(const float4*)(Wp + (size_t)(k0 + rowB) * N + colB);
        __syncthreads();
#pragma unroll
        for (int kk = 0; kk < 8; kk++) {
            float4 a0 = *(const float4*)&As[kk][tr * 8];
            float4 a1 = *(const float4*)&As[kk][tr * 8 + 4];
            float4 b0 = *(const float4*)&Bs[kk][tc * 8];
            float4 b1 = *(const float4*)&Bs[kk][tc * 8 + 4];
            float ar[8] = {a0.x, a0.y, a0.z, a0.w, a1.x, a1.y, a1.z, a1.w};
            float br[8] = {b0.x, b0.y, b0.z, b0.w, b1.x, b1.y, b1.z, b1.w};
#pragma unroll
            for (int i = 0; i < 8; i++)
#pragma unroll
                for (int j = 0; j < 8; j++)
                    acc[i][j] = fmaf(ar[i], br[j], acc[i][j]);
        }
        __syncthreads();
    }

#pragma unroll
    for (int i = 0; i < 8; i++) {
        int m = bm * 128 + tr * 8 + i;
        int b = m >> 11;
        int s = m & (NS - 1);
#pragma unroll
        for (int j = 0; j < 8; j++) {
            int n = bn * 128 + tc * 8 + j;
            float v = acc[i][j];
            if (mode == 0) {
                int h = n >> 6, d = n & 63;
                g_Q[(((size_t)b * NH + h) * NS + s) * ND + d] = v;
            } else if (mode == 1) {
                int c2 = n >> 9;
                int h = (n >> 6) & 7, d = n & 63;
                float* dst = c2 ? g_V : g_K;
                dst[(((size_t)b * NH + h) * NS + s) * ND + d] = v;
            } else {
                g_Y[(size_t)m * NE + n] = v + bff[n] + resid[(size_t)m * NE + n];
            }
        }
    }
}

// ============================================================
// Flash attention: Br=128 q-rows, Bc=64 keys per iter, D=64.
// 256 threads: ty(0..15) owns 8 rows, tx(0..15) owns 4 cols.
// Online softmax; bias streamed from gmem; mask -> exact -1e9.
// ============================================================
#define BR 128
#define BC 64
#define LDP 68   // padded smem row stride (floats), 16B-aligned rows

__global__ __launch_bounds__(256) void attn_kernel(
    const float* __restrict__ bias, const int* __restrict__ mask,
    const float* __restrict__ gamma_f)
{
    extern __shared__ float sm[];
    float* Qs = sm;                    // BR x LDP
    float* Ks = Qs + BR * LDP;         // BC x LDP
    float* Vs = Ks + BC * LDP;         // BC x LDP
    float* Ps = Vs + BC * LDP;         // BR x LDP
    int* msk = (int*)(Ps + BR * LDP);  // BC ints

    const int qt = blockIdx.x, h = blockIdx.y, b = blockIdx.z;
    const int tid = threadIdx.x;
    const int ty = tid >> 4, tx = tid & 15;
    const size_t bh = (size_t)b * NH + h;
    const float* Qg = g_Q + (bh * NS + (size_t)qt * BR) * ND;
    const float* Kg = g_K + bh * NS * ND;
    const float* Vg = g_V + bh * NS * ND;
    const float gamma = gamma_f[h];
    const float* biasBase = bias + ((size_t)b * NS + (size_t)qt * BR) * NS;
    const int* maskBase = mask + (size_t)b * NS;

    // load Q tile
    for (int t = tid; t < BR * (ND / 4); t += 256) {
        int r = t >> 4, c4 = (t & 15) << 2;
        *(float4*)&Qs[r * LDP + c4] = *(const float4*)(Qg + r * ND + c4);
    }

    float mrow[8], lrow[8], O[8][4];
#pragma unroll
    for (int i = 0; i < 8; i++) {
        mrow[i] = -3.0e38f;
        lrow[i] = 0.f;
#pragma unroll
        for (int j = 0; j < 4; j++) O[i][j] = 0.f;
    }

    for (int kt = 0; kt < NS / BC; kt++) {
        __syncthreads();   // prev iteration fully done before overwriting K/V
        const float* Kt = Kg + (size_t)kt * BC * ND;
        const float* Vt = Vg + (size_t)kt * BC * ND;
        for (int t = tid; t < BC * (ND / 4); t += 256) {
            int r = t >> 4, c4 = (t & 15) << 2;
            *(float4*)&Ks[r * LDP + c4] = *(const float4*)(Kt + r * ND + c4);
            *(float4*)&Vs[r * LDP + c4] = *(const float4*)(Vt + r * ND + c4);
        }
        if (tid < BC) msk[tid] = maskBase[kt * BC + tid];
        __syncthreads();

        // ---- S = Q K^T (BR x BC), microtile 8x4 ----
        float acc[8][4];
#pragma unroll
        for (int i = 0; i < 8; i++)
#pragma unroll
            for (int j = 0; j < 4; j++) acc[i][j] = 0.f;

        for (int d0 = 0; d0 < ND; d0 += 4) {
            float4 q4[8], k4[4];
#pragma unroll
            for (int i = 0; i < 8; i++)
                q4[i] = *(const float4*)&Qs[(ty * 8 + i) * LDP + d0];
#pragma unroll
            for (int j = 0; j < 4; j++)
                k4[j] = *(const float4*)&Ks[(tx * 4 + j) * LDP + d0];
#pragma unroll
            for (int i = 0; i < 8; i++)
#pragma unroll
                for (int j = 0; j < 4; j++) {
                    acc[i][j] = fmaf(q4[i].x, k4[j].x, acc[i][j]);
                    acc[i][j] = fmaf(q4[i].y, k4[j].y, acc[i][j]);
                    acc[i][j] = fmaf(q4[i].z, k4[j].z, acc[i][j]);
                    acc[i][j] = fmaf(q4[i].w, k4[j].w, acc[i][j]);
                }
        }

        // ---- bias + mask + online softmax (row reduce over 16 lanes) ----
        int mk0 = msk[tx * 4 + 0], mk1 = msk[tx * 4 + 1];
        int mk2 = msk[tx * 4 + 2], mk3 = msk[tx * 4 + 3];
#pragma unroll
        for (int i = 0; i < 8; i++) {
            int r = ty * 8 + i;
            float4 b4 = *(const float4*)(biasBase + (size_t)r * NS + kt * BC + tx * 4);
            float sv[4];
            sv[0] = mk0 ? -1e9f : acc[i][0] * 0.125f + gamma * b4.x;
            sv[1] = mk1 ? -1e9f : acc[i][1] * 0.125f + gamma * b4.y;
            sv[2] = mk2 ? -1e9f : acc[i][2] * 0.125f + gamma * b4.z;
            sv[3] = mk3 ? -1e9f : acc[i][3] * 0.125f + gamma * b4.w;
            float mx = fmaxf(fmaxf(sv[0], sv[1]), fmaxf(sv[2], sv[3]));
#pragma unroll
            for (int o = 8; o; o >>= 1)
                mx = fmaxf(mx, __shfl_xor_sync(0xffffffffu, mx, o, 16));
            float mnew = fmaxf(mrow[i], mx);
            float corr = __expf(mrow[i] - mnew);
            float rs = 0.f;
#pragma unroll
            for (int j = 0; j < 4; j++) {
                sv[j] = __expf(sv[j] - mnew);
                rs += sv[j];
            }
#pragma unroll
            for (int o = 8; o; o >>= 1)
                rs += __shfl_xor_sync(0xffffffffu, rs, o, 16);
            lrow[i] = lrow[i] * corr + rs;
            mrow[i] = mnew;
#pragma unroll
            for (int j = 0; j < 4; j++) O[i][j] *= corr;
            *(float4*)&Ps[r * LDP + tx * 4] = make_float4(sv[0], sv[1], sv[2], sv[3]);
        }
        __syncthreads();

        // ---- O += P V (BR x 64), microtile 8 rows x 4 d-cols ----
        for (int k0 = 0; k0 < BC; k0 += 4) {
            float4 v0 = *(const float4*)&Vs[(k0 + 0) * LDP + tx * 4];
            float4 v1 = *(const float4*)&Vs[(k0 + 1) * LDP + tx * 4];
            float4 v2 = *(const float4*)&Vs[(k0 + 2) * LDP + tx * 4];
            float4 v3 = *(const float4*)&Vs[(k0 + 3) * LDP + tx * 4];
#pragma unroll
            for (int i = 0; i < 8; i++) {
                float4 p = *(const float4*)&Ps[(ty * 8 + i) * LDP + k0];
                O[i][0] += p.x * v0.x + p.y * v1.x + p.z * v2.x + p.w * v3.x;
                O[i][1] += p.x * v0.y + p.y * v1.y + p.z * v2.y + p.w * v3.y;
                O[i][2] += p.x * v0.z + p.y * v1.z + p.z * v2.z + p.w * v3.z;
                O[i][3] += p.x * v0.w + p.y * v1.w + p.z * v2.w + p.w * v3.w;
            }
        }
    }

    // ---- epilogue: att[(b*S+q)*512 + h*64 + c] = O / l ----
#pragma unroll
    for (int i = 0; i < 8; i++) {
        int q = qt * BR + ty * 8 + i;
        float inv = 1.f / lrow[i];
        float4 o4 = make_float4(O[i][0] * inv, O[i][1] * inv,
                                O[i][2] * inv, O[i][3] * inv);
        *(float4*)&g_att[((size_t)b * NS + q) * NE + h * ND + tx * 4] = o4;
    }
}

// ============================================================
// LayerNorm over rows of g_Y (512 elems), 128 threads/row.
// ============================================================
__global__ __launch_bounds__(128) void ln_kernel(
    const float* __restrict__ ln_g, const float* __restrict__ ln_b,
    float* __restrict__ out)
{
    __shared__ float red[8];
    int row = blockIdx.x;
    int tid = threadIdx.x;
    const float* y = g_Y + (size_t)row * NE;
    float4 v = ((const float4*)y)[tid];
    float s = v.x + v.y + v.z + v.w;
    float s2 = v.x * v.x + v.y * v.y + v.z * v.z + v.w * v.w;
#pragma unroll
    for (int o = 16; o; o >>= 1) {
        s += __shfl_xor_sync(0xffffffffu, s, o);
        s2 += __shfl_xor_sync(0xffffffffu, s2, o);
    }
    int w = tid >> 5;
    if ((tid & 31) == 0) { red[w] = s; red[4 + w] = s2; }
    __syncthreads();
    s = red[0] + red[1] + red[2] + red[3];
    s2 = red[4] + red[5] + red[6] + red[7];
    float mu = s * (1.f / NE);
    float var = s2 * (1.f / NE) - mu * mu;
    float rstd = rsqrtf(var + 1e-5f);
    float4 g = ((const float4*)ln_g)[tid];
    float4 be = ((const float4*)ln_b)[tid];
    float4 o;
    o.x = (v.x - mu) * rstd * g.x + be.x;
    o.y = (v.y - mu) * rstd * g.y + be.y;
    o.z = (v.z - mu) * rstd * g.z + be.z;
    o.w = (v.w - mu) * rstd * g.w + be.w;
    ((float4*)(out + (size_t)row * NE))[tid] = o;
}

// ============================================================
extern "C" void kernel_launch(void* const* d_in, const int* in_sizes, int n_in,
                              void* d_out, int out_size)
{
    const float* x_p     = (const float*)d_in[0];
    const float* x_pcre  = (const float*)d_in[1];
    const float* bias    = (const float*)d_in[2];
    const int*   mask    = (const int*)d_in[3];   // bool -> int32 assumption
    const float* Wq      = (const float*)d_in[4];
    const float* Wkv     = (const float*)d_in[5];
    const float* Wff     = (const float*)d_in[6];
    const float* bff     = (const float*)d_in[7];
    const float* gamma_f = (const float*)d_in[8];
    const float* ln_g    = (const float*)d_in[9];
    const float* ln_b    = (const float*)d_in[10];
    float* out = (float*)d_out;

    const int MROWS = NB * NS;  // 16384

    // Q projection: (16384x512)@(512x512)
    sgemm_fused<<<dim3(512 / 128, MROWS / 128), 256>>>(x_p, Wq, nullptr, nullptr, 512, 0);
    // KV projection: (16384x512)@(512x1024)
    sgemm_fused<<<dim3(1024 / 128, MROWS / 128), 256>>>(x_pcre, Wkv, nullptr, nullptr, 1024, 1);

    // attention
    const int smem_att = (BR * LDP * 2 + BC * LDP * 2) * (int)sizeof(float) + BC * (int)sizeof(int);
    cudaFuncSetAttribute(attn_kernel, cudaFuncAttributeMaxDynamicSharedMemorySize, smem_att);
    attn_kernel<<<dim3(NS / BR, NH, NB), 256, smem_att>>>(bias, mask, gamma_f);

    // FF + bias + residual
    sgemm_fused<<<dim3(512 / 128, MROWS / 128), 256>>>(nullptr, Wff, bff, x_p, 512, 2);

    // LayerNorm
    ln_kernel<<<MROWS, 128>>>(ln_g, ln_b, out);
}

// round 3
// speedup vs baseline: 1.0031x; 1.0031x over previous
#include <cuda_runtime.h>
#include <math.h>
#include <stdint.h>

#define NB 8
#define NS 2048
#define NE 512
#define NH 8
#define ND 64

// ---- scratch (static device globals; no allocation) ----
__device__ float g_Q[(size_t)NB * NH * NS * ND];   // (b,h,s,d)
__device__ float g_K[(size_t)NB * NH * NS * ND];
__device__ float g_V[(size_t)NB * NH * NS * ND];
__device__ float g_att[(size_t)NB * NS * NE];      // (b*s, h*64+d)
__device__ float g_Y[(size_t)NB * NS * NE];

// ============================================================
// Fused SGEMM: 128x128x8 block tile, 8x8 per-thread microtile.
// mode 0: X=x_p,  W=Wq  (N=512)  -> scatter into g_Q (b,h,s,d)
// mode 1: X=x_pcre, W=Wkv (N=1024)-> scatter into g_K / g_V
// mode 2: X=g_att, W=Wff (N=512) -> + bff + resid -> g_Y
// ============================================================
__global__ __launch_bounds__(256) void sgemm_fused(
    const float* __restrict__ X, const float* __restrict__ W,
    const float* __restrict__ bff, const float* __restrict__ resid,
    int N, int mode)
{
    __shared__ float As[8][128];   // transposed A tile
    __shared__ float Bs[8][128];
    const int K = NE;
    const int tid = threadIdx.x;
    const int bn = blockIdx.x, bm = blockIdx.y;
    const int rowA = tid >> 1, colA = (tid & 1) << 2;
    const int rowB = tid >> 5, colB = (tid & 31) << 2;
    const int tr = tid >> 4, tc = tid & 15;

    const float* Xbase = (mode == 2) ? g_att : X;
    const float* Xp = Xbase + (size_t)bm * 128 * K;
    const float* Wp = W + (size_t)bn * 128;

    float acc[8][8];
#pragma unroll
    for (int i = 0; i < 8; i++)
#pragma unroll
        for (int j = 0; j < 8; j++) acc[i][j] = 0.f;

    for (int k0 = 0; k0 < K; k0 += 8) {
        float4 a = *(const float4*)(Xp + (size_t)rowA * K + k0 + colA);
        As[colA + 0][rowA] = a.x;
        As[colA + 1][rowA] = a.y;
        As[colA + 2][rowA] = a.z;
        As[colA + 3][rowA] = a.w;
        *(float4*)&Bs[rowB][colB] =
            *(const float4*)(Wp + (size_t)(k0 + rowB) * N + colB);
        __syncthreads();
#pragma unroll
        for (int kk = 0; kk < 8; kk++) {
            float4 a0 = *(const float4*)&As[kk][tr * 8];
            float4 a1 = *(const float4*)&As[kk][tr * 8 + 4];
            float4 b0 = *(const float4*)&Bs[kk][tc * 8];
            float4 b1 = *(const float4*)&Bs[kk][tc * 8 + 4];
            float ar[8] = {a0.x, a0.y, a0.z, a0.w, a1.x, a1.y, a1.z, a1.w};
            float br[8] = {b0.x, b0.y, b0.z, b0.w, b1.x, b1.y, b1.z, b1.w};
#pragma unroll
            for (int i = 0; i < 8; i++)
#pragma unroll
                for (int j = 0; j < 8; j++)
                    acc[i][j] = fmaf(ar[i], br[j], acc[i][j]);
        }
        __syncthreads();
    }

#pragma unroll
    for (int i = 0; i < 8; i++) {
        int m = bm * 128 + tr * 8 + i;
        int b = m >> 11;
        int s = m & (NS - 1);
#pragma unroll
        for (int j = 0; j < 8; j++) {
            int n = bn * 128 + tc * 8 + j;
            float v = acc[i][j];
            if (mode == 0) {
                int h = n >> 6, d = n & 63;
                g_Q[(((size_t)b * NH + h) * NS + s) * ND + d] = v;
            } else if (mode == 1) {
                int c2 = n >> 9;
                int h = (n >> 6) & 7, d = n & 63;
                float* dst = c2 ? g_V : g_K;
                dst[(((size_t)b * NH + h) * NS + s) * ND + d] = v;
            } else {
                g_Y[(size_t)m * NE + n] = v + bff[n] + resid[(size_t)m * NE + n];
            }
        }
    }
}

// ============================================================
// Flash attention: Br=128 q-rows, Bc=64 keys per iter, D=64.
// 256 threads: ty(0..15) owns 8 rows, tx(0..15) owns 4 cols.
// Online softmax; bias streamed from gmem; mask -> exact -1e9.
// ============================================================
#define BR 128
#define BC 64
#define LDP 68   // padded smem row stride (floats), 16B-aligned rows

__global__ __launch_bounds__(256) void attn_kernel(
    const float* __restrict__ bias, const int* __restrict__ mask,
    const float* __restrict__ gamma_f)
{
    extern __shared__ float sm[];
    float* Qs = sm;                    // BR x LDP
    float* Ks = Qs + BR * LDP;         // BC x LDP
    float* Vs = Ks + BC * LDP;         // BC x LDP
    float* Ps = Vs + BC * LDP;         // BR x LDP
    int* msk = (int*)(Ps + BR * LDP);  // BC ints

    const int qt = blockIdx.x, h = blockIdx.y, b = blockIdx.z;
    const int tid = threadIdx.x;
    const int ty = tid >> 4, tx = tid & 15;
    const size_t bh = (size_t)b * NH + h;
    const float* Qg = g_Q + (bh * NS + (size_t)qt * BR) * ND;
    const float* Kg = g_K + bh * NS * ND;
    const float* Vg = g_V + bh * NS * ND;
    const float gamma = gamma_f[h];
    const float* biasBase = bias + ((size_t)b * NS + (size_t)qt * BR) * NS;
    const int* maskBase = mask + (size_t)b * NS;

    // load Q tile
    for (int t = tid; t < BR * (ND / 4); t += 256) {
        int r = t >> 4, c4 = (t & 15) << 2;
        *(float4*)&Qs[r * LDP + c4] = *(const float4*)(Qg + r * ND + c4);
    }

    float mrow[8], lrow[8], O[8][4];
#pragma unroll
    for (int i = 0; i < 8; i++) {
        mrow[i] = -3.0e38f;
        lrow[i] = 0.f;
#pragma unroll
        for (int j = 0; j < 4; j++) O[i][j] = 0.f;
    }

    for (int kt = 0; kt < NS / BC; kt++) {
        __syncthreads();   // prev iteration fully done before overwriting K/V
        const float* Kt = Kg + (size_t)kt * BC * ND;
        const float* Vt = Vg + (size_t)kt * BC * ND;
        for (int t = tid; t < BC * (ND / 4); t += 256) {
            int r = t >> 4, c4 = (t & 15) << 2;
            *(float4*)&Ks[r * LDP + c4] = *(const float4*)(Kt + r * ND + c4);
            *(float4*)&Vs[r * LDP + c4] = *(const float4*)(Vt + r * ND + c4);
        }
        if (tid < BC) msk[tid] = maskBase[kt * BC + tid];
        __syncthreads();

        // ---- S = Q K^T (BR x BC), microtile 8x4 ----
        float acc[8][4];
#pragma unroll
        for (int i = 0; i < 8; i++)
#pragma unroll
            for (int j = 0; j < 4; j++) acc[i][j] = 0.f;

        for (int d0 = 0; d0 < ND; d0 += 4) {
            float4 q4[8], k4[4];
#pragma unroll
            for (int i = 0; i < 8; i++)
                q4[i] = *(const float4*)&Qs[(ty * 8 + i) * LDP + d0];
#pragma unroll
            for (int j = 0; j < 4; j++)
                k4[j] = *(const float4*)&Ks[(tx * 4 + j) * LDP + d0];
#pragma unroll
            for (int i = 0; i < 8; i++)
#pragma unroll
                for (int j = 0; j < 4; j++) {
                    acc[i][j] = fmaf(q4[i].x, k4[j].x, acc[i][j]);
                    acc[i][j] = fmaf(q4[i].y, k4[j].y, acc[i][j]);
                    acc[i][j] = fmaf(q4[i].z, k4[j].z, acc[i][j]);
                    acc[i][j] = fmaf(q4[i].w, k4[j].w, acc[i][j]);
                }
        }

        // ---- bias + mask + online softmax (row reduce over 16 lanes) ----
        int mk0 = msk[tx * 4 + 0], mk1 = msk[tx * 4 + 1];
        int mk2 = msk[tx * 4 + 2], mk3 = msk[tx * 4 + 3];
#pragma unroll
        for (int i = 0; i < 8; i++) {
            int r = ty * 8 + i;
            float4 b4 = *(const float4*)(biasBase + (size_t)r * NS + kt * BC + tx * 4);
            float sv[4];
            sv[0] = mk0 ? -1e9f : acc[i][0] * 0.125f + gamma * b4.x;
            sv[1] = mk1 ? -1e9f : acc[i][1] * 0.125f + gamma * b4.y;
            sv[2] = mk2 ? -1e9f : acc[i][2] * 0.125f + gamma * b4.z;
            sv[3] = mk3 ? -1e9f : acc[i][3] * 0.125f + gamma * b4.w;
            float mx = fmaxf(fmaxf(sv[0], sv[1]), fmaxf(sv[2], sv[3]));
#pragma unroll
            for (int o = 8; o; o >>= 1)
                mx = fmaxf(mx, __shfl_xor_sync(0xffffffffu, mx, o, 16));
            float mnew = fmaxf(mrow[i], mx);
            float corr = __expf(mrow[i] - mnew);
            float rs = 0.f;
#pragma unroll
            for (int j = 0; j < 4; j++) {
                sv[j] = __expf(sv[j] - mnew);
                rs += sv[j];
            }
#pragma unroll
            for (int o = 8; o; o >>= 1)
                rs += __shfl_xor_sync(0xffffffffu, rs, o, 16);
            lrow[i] = lrow[i] * corr + rs;
            mrow[i] = mnew;
#pragma unroll
            for (int j = 0; j < 4; j++) O[i][j] *= corr;
            *(float4*)&Ps[r * LDP + tx * 4] = make_float4(sv[0], sv[1], sv[2], sv[3]);
        }
        __syncthreads();

        // ---- O += P V (BR x 64), microtile 8 rows x 4 d-cols ----
        for (int k0 = 0; k0 < BC; k0 += 4) {
            float4 v0 = *(const float4*)&Vs[(k0 + 0) * LDP + tx * 4];
            float4 v1 = *(const float4*)&Vs[(k0 + 1) * LDP + tx * 4];
            float4 v2 = *(const float4*)&Vs[(k0 + 2) * LDP + tx * 4];
            float4 v3 = *(const float4*)&Vs[(k0 + 3) * LDP + tx * 4];
#pragma unroll
            for (int i = 0; i < 8; i++) {
                float4 p = *(const float4*)&Ps[(ty * 8 + i) * LDP + k0];
                O[i][0] += p.x * v0.x + p.y * v1.x + p.z * v2.x + p.w * v3.x;
                O[i][1] += p.x * v0.y + p.y * v1.y + p.z * v2.y + p.w * v3.y;
                O[i][2] += p.x * v0.z + p.y * v1.z + p.z * v2.z + p.w * v3.z;
                O[i][3] += p.x * v0.w + p.y * v1.w + p.z * v2.w + p.w * v3.w;
            }
        }
    }

    // ---- epilogue: att[(b*S+q)*512 + h*64 + c] = O / l ----
#pragma unroll
    for (int i = 0; i < 8; i++) {
        int q = qt * BR + ty * 8 + i;
        float inv = 1.f / lrow[i];
        float4 o4 = make_float4(O[i][0] * inv, O[i][1] * inv,
                                O[i][2] * inv, O[i][3] * inv);
        *(float4*)&g_att[((size_t)b * NS + q) * NE + h * ND + tx * 4] = o4;
    }
}

// ============================================================
// LayerNorm over rows of g_Y (512 elems), 128 threads/row.
// ============================================================
__global__ __launch_bounds__(128) void ln_kernel(
    const float* __restrict__ ln_g, const float* __restrict__ ln_b,
    float* __restrict__ out)
{
    __shared__ float red[8];
    int row = blockIdx.x;
    int tid = threadIdx.x;
    const float* y = g_Y + (size_t)row * NE;
    float4 v = ((const float4*)y)[tid];
    float s = v.x + v.y + v.z + v.w;
    float s2 = v.x * v.x + v.y * v.y + v.z * v.z + v.w * v.w;
#pragma unroll
    for (int o = 16; o; o >>= 1) {
        s += __shfl_xor_sync(0xffffffffu, s, o);
        s2 += __shfl_xor_sync(0xffffffffu, s2, o);
    }
    int w = tid >> 5;
    if ((tid & 31) == 0) { red[w] = s; red[4 + w] = s2; }
    __syncthreads();
    s = red[0] + red[1] + red[2] + red[3];
    s2 = red[4] + red[5] + red[6] + red[7];
    float mu = s * (1.f / NE);
    float var = s2 * (1.f / NE) - mu * mu;
    float rstd = rsqrtf(var + 1e-5f);
    float4 g = ((const float4*)ln_g)[tid];
    float4 be = ((const float4*)ln_b)[tid];
    float4 o;
    o.x = (v.x - mu) * rstd * g.x + be.x;
    o.y = (v.y - mu) * rstd * g.y + be.y;
    o.z = (v.z - mu) * rstd * g.z + be.z;
    o.w = (v.w - mu) * rstd * g.w + be.w;
    ((float4*)(out + (size_t)row * NE))[tid] = o;
}

// ============================================================
extern "C" void kernel_launch(void* const* d_in, const int* in_sizes, int n_in,
                              void* d_out, int out_size)
{
    const float* x_p     = (const float*)d_in[0];
    const float* x_pcre  = (const float*)d_in[1];
    const float* bias    = (const float*)d_in[2];
    const int*   mask    = (const int*)d_in[3];   // bool -> int32 assumption
    const float* Wq      = (const float*)d_in[4];
    const float* Wkv     = (const float*)d_in[5];
    const float* Wff     = (const float*)d_in[6];
    const float* bff     = (const float*)d_in[7];
    const float* gamma_f = (const float*)d_in[8];
    const float* ln_g    = (const float*)d_in[9];
    const float* ln_b    = (const float*)d_in[10];
    float* out = (float*)d_out;

    const int MROWS = NB * NS;  // 16384

    // Q projection: (16384x512)@(512x512)
    sgemm_fused<<<dim3(512 / 128, MROWS / 128), 256>>>(x_p, Wq, nullptr, nullptr, 512, 0);
    // KV projection: (16384x512)@(512x1024)
    sgemm_fused<<<dim3(1024 / 128, MROWS / 128), 256>>>(x_pcre, Wkv, nullptr, nullptr, 1024, 1);

    // attention
    const int smem_att = (BR * LDP * 2 + BC * LDP * 2) * (int)sizeof(float) + BC * (int)sizeof(int);
    cudaFuncSetAttribute(attn_kernel, cudaFuncAttributeMaxDynamicSharedMemorySize, smem_att);
    attn_kernel<<<dim3(NS / BR, NH, NB), 256, smem_att>>>(bias, mask, gamma_f);

    // FF + bias + residual
    sgemm_fused<<<dim3(512 / 128, MROWS / 128), 256>>>(nullptr, Wff, bff, x_p, 512, 2);

    // LayerNorm
    ln_kernel<<<MROWS, 128>>>(ln_g, ln_b, out);
}

// round 4
// speedup vs baseline: 1.0032x; 1.0001x over previous
#include <cuda_runtime.h>
#include <math.h>
#include <stdint.h>

#define NB 8
#define NS 2048
#define NE 512
#define NH 8
#define ND 64

// ---- scratch (static device globals; no allocation) ----
__device__ float g_Q[(size_t)NB * NH * NS * ND];   // (b,h,s,d)
__device__ float g_K[(size_t)NB * NH * NS * ND];
__device__ float g_V[(size_t)NB * NH * NS * ND];
__device__ float g_att[(size_t)NB * NS * NE];      // (b*s, h*64+d)
__device__ float g_Y[(size_t)NB * NS * NE];

// ============================================================
// Fused SGEMM: 128x128x8 block tile, 8x8 per-thread microtile.
// mode 0: X=x_p,  W=Wq  (N=512)  -> scatter into g_Q (b,h,s,d)
// mode 1: X=x_pcre, W=Wkv (N=1024)-> scatter into g_K / g_V
// mode 2: X=g_att, W=Wff (N=512) -> + bff + resid -> g_Y
// ============================================================
__global__ __launch_bounds__(256) void sgemm_fused(
    const float* __restrict__ X, const float* __restrict__ W,
    const float* __restrict__ bff, const float* __restrict__ resid,
    int N, int mode)
{
    __shared__ float As[8][128];   // transposed A tile
    __shared__ float Bs[8][128];
    const int K = NE;
    const int tid = threadIdx.x;
    const int bn = blockIdx.x, bm = blockIdx.y;
    const int rowA = tid >> 1, colA = (tid & 1) << 2;
    const int rowB = tid >> 5, colB = (tid & 31) << 2;
    const int tr = tid >> 4, tc = tid & 15;

    const float* Xbase = (mode == 2) ? g_att : X;
    const float* Xp = Xbase + (size_t)bm * 128 * K;
    const float* Wp = W + (size_t)bn * 128;

    float acc[8][8];
#pragma unroll
    for (int i = 0; i < 8; i++)
#pragma unroll
        for (int j = 0; j < 8; j++) acc[i][j] = 0.f;

    for (int k0 = 0; k0 < K; k0 += 8) {
        float4 a = *(const float4*)(Xp + (size_t)rowA * K + k0 + colA);
        As[colA + 0][rowA] = a.x;
        As[colA + 1][rowA] = a.y;
        As[colA + 2][rowA] = a.z;
        As[colA + 3][rowA] = a.w;
        *(float4*)&Bs[rowB][colB] =
            *(const float4*)(Wp + (size_t)(k0 + rowB) * N + colB);
        __syncthreads();
#pragma unroll
        for (int kk = 0; kk < 8; kk++) {
            float4 a0 = *(const float4*)&As[kk][tr * 8];
            float4 a1 = *(const float4*)&As[kk][tr * 8 + 4];
            float4 b0 = *(const float4*)&Bs[kk][tc * 8];
            float4 b1 = *(const float4*)&Bs[kk][tc * 8 + 4];
            float ar[8] = {a0.x, a0.y, a0.z, a0.w, a1.x, a1.y, a1.z, a1.w};
            float br[8] = {b0.x, b0.y, b0.z, b0.w, b1.x, b1.y, b1.z, b1.w};
#pragma unroll
            for (int i = 0; i < 8; i++)
#pragma unroll
                for (int j = 0; j < 8; j++)
                    acc[i][j] = fmaf(ar[i], br[j], acc[i][j]);
        }
        __syncthreads();
    }

#pragma unroll
    for (int i = 0; i < 8; i++) {
        int m = bm * 128 + tr * 8 + i;
        int b = m >> 11;
        int s = m & (NS - 1);
#pragma unroll
        for (int j = 0; j < 8; j++) {
            int n = bn * 128 + tc * 8 + j;
            float v = acc[i][j];
            if (mode == 0) {
                int h = n >> 6, d = n & 63;
                g_Q[(((size_t)b * NH + h) * NS + s) * ND + d] = v;
            } else if (mode == 1) {
                int c2 = n >> 9;
                int h = (n >> 6) & 7, d = n & 63;
                float* dst = c2 ? g_V : g_K;
                dst[(((size_t)b * NH + h) * NS + s) * ND + d] = v;
            } else {
                g_Y[(size_t)m * NE + n] = v + bff[n] + resid[(size_t)m * NE + n];
            }
        }
    }
}

// ============================================================
// Flash attention: Br=128 q-rows, Bc=64 keys per iter, D=64.
// 256 threads: ty(0..15) owns 8 rows, tx(0..15) owns 4 cols.
// Online softmax; bias streamed from gmem; mask -> exact -1e9.
// ============================================================
#define BR 128
#define BC 64
#define LDP 68   // padded smem row stride (floats), 16B-aligned rows

__global__ __launch_bounds__(256) void attn_kernel(
    const float* __restrict__ bias, const int* __restrict__ mask,
    const float* __restrict__ gamma_f)
{
    extern __shared__ float sm[];
    float* Qs = sm;                    // BR x LDP
    float* Ks = Qs + BR * LDP;         // BC x LDP
    float* Vs = Ks + BC * LDP;         // BC x LDP
    float* Ps = Vs + BC * LDP;         // BR x LDP
    int* msk = (int*)(Ps + BR * LDP);  // BC ints

    const int qt = blockIdx.x, h = blockIdx.y, b = blockIdx.z;
    const int tid = threadIdx.x;
    const int ty = tid >> 4, tx = tid & 15;
    const size_t bh = (size_t)b * NH + h;
    const float* Qg = g_Q + (bh * NS + (size_t)qt * BR) * ND;
    const float* Kg = g_K + bh * NS * ND;
    const float* Vg = g_V + bh * NS * ND;
    const float gamma = gamma_f[h];
    const float* biasBase = bias + ((size_t)b * NS + (size_t)qt * BR) * NS;
    const int* maskBase = mask + (size_t)b * NS;

    // load Q tile
    for (int t = tid; t < BR * (ND / 4); t += 256) {
        int r = t >> 4, c4 = (t & 15) << 2;
        *(float4*)&Qs[r * LDP + c4] = *(const float4*)(Qg + r * ND + c4);
    }

    float mrow[8], lrow[8], O[8][4];
#pragma unroll
    for (int i = 0; i < 8; i++) {
        mrow[i] = -3.0e38f;
        lrow[i] = 0.f;
#pragma unroll
        for (int j = 0; j < 4; j++) O[i][j] = 0.f;
    }

    for (int kt = 0; kt < NS / BC; kt++) {
        __syncthreads();   // prev iteration fully done before overwriting K/V
        const float* Kt = Kg + (size_t)kt * BC * ND;
        const float* Vt = Vg + (size_t)kt * BC * ND;
        for (int t = tid; t < BC * (ND / 4); t += 256) {
            int r = t >> 4, c4 = (t & 15) << 2;
            *(float4*)&Ks[r * LDP + c4] = *(const float4*)(Kt + r * ND + c4);
            *(float4*)&Vs[r * LDP + c4] = *(const float4*)(Vt + r * ND + c4);
        }
        if (tid < BC) msk[tid] = maskBase[kt * BC + tid];
        __syncthreads();

        // ---- S = Q K^T (BR x BC), microtile 8x4 ----
        float acc[8][4];
#pragma unroll
        for (int i = 0; i < 8; i++)
#pragma unroll
            for (int j = 0; j < 4; j++) acc[i][j] = 0.f;

        for (int d0 = 0; d0 < ND; d0 += 4) {
            float4 q4[8], k4[4];
#pragma unroll
            for (int i = 0; i < 8; i++)
                q4[i] = *(const float4*)&Qs[(ty * 8 + i) * LDP + d0];
#pragma unroll
            for (int j = 0; j < 4; j++)
                k4[j] = *(const float4*)&Ks[(tx * 4 + j) * LDP + d0];
#pragma unroll
            for (int i = 0; i < 8; i++)
#pragma unroll
                for (int j = 0; j < 4; j++) {
                    acc[i][j] = fmaf(q4[i].x, k4[j].x, acc[i][j]);
                    acc[i][j] = fmaf(q4[i].y, k4[j].y, acc[i][j]);
                    acc[i][j] = fmaf(q4[i].z, k4[j].z, acc[i][j]);
                    acc[i][j] = fmaf(q4[i].w, k4[j].w, acc[i][j]);
                }
        }

        // ---- bias + mask + online softmax (row reduce over 16 lanes) ----
        int mk0 = msk[tx * 4 + 0], mk1 = msk[tx * 4 + 1];
        int mk2 = msk[tx * 4 + 2], mk3 = msk[tx * 4 + 3];
#pragma unroll
        for (int i = 0; i < 8; i++) {
            int r = ty * 8 + i;
            float4 b4 = *(const float4*)(biasBase + (size_t)r * NS + kt * BC + tx * 4);
            float sv[4];
            sv[0] = mk0 ? -1e9f : acc[i][0] * 0.125f + gamma * b4.x;
            sv[1] = mk1 ? -1e9f : acc[i][1] * 0.125f + gamma * b4.y;
            sv[2] = mk2 ? -1e9f : acc[i][2] * 0.125f + gamma * b4.z;
            sv[3] = mk3 ? -1e9f : acc[i][3] * 0.125f + gamma * b4.w;
            float mx = fmaxf(fmaxf(sv[0], sv[1]), fmaxf(sv[2], sv[3]));
#pragma unroll
            for (int o = 8; o; o >>= 1)
                mx = fmaxf(mx, __shfl_xor_sync(0xffffffffu, mx, o, 16));
            float mnew = fmaxf(mrow[i], mx);
            float corr = __expf(mrow[i] - mnew);
            float rs = 0.f;
#pragma unroll
            for (int j = 0; j < 4; j++) {
                sv[j] = __expf(sv[j] - mnew);
                rs += sv[j];
            }
#pragma unroll
            for (int o = 8; o; o >>= 1)
                rs += __shfl_xor_sync(0xffffffffu, rs, o, 16);
            lrow[i] = lrow[i] * corr + rs;
            mrow[i] = mnew;
#pragma unroll
            for (int j = 0; j < 4; j++) O[i][j] *= corr;
            *(float4*)&Ps[r * LDP + tx * 4] = make_float4(sv[0], sv[1], sv[2], sv[3]);
        }
        __syncthreads();

        // ---- O += P V (BR x 64), microtile 8 rows x 4 d-cols ----
        for (int k0 = 0; k0 < BC; k0 += 4) {
            float4 v0 = *(const float4*)&Vs[(k0 + 0) * LDP + tx * 4];
            float4 v1 = *(const float4*)&Vs[(k0 + 1) * LDP + tx * 4];
            float4 v2 = *(const float4*)&Vs[(k0 + 2) * LDP + tx * 4];
            float4 v3 = *(const float4*)&Vs[(k0 + 3) * LDP + tx * 4];
#pragma unroll
            for (int i = 0; i < 8; i++) {
                float4 p = *(const float4*)&Ps[(ty * 8 + i) * LDP + k0];
                O[i][0] += p.x * v0.x + p.y * v1.x + p.z * v2.x + p.w * v3.x;
                O[i][1] += p.x * v0.y + p.y * v1.y + p.z * v2.y + p.w * v3.y;
                O[i][2] += p.x * v0.z + p.y * v1.z + p.z * v2.z + p.w * v3.z;
                O[i][3] += p.x * v0.w + p.y * v1.w + p.z * v2.w + p.w * v3.w;
            }
        }
    }

    // ---- epilogue: att[(b*S+q)*512 + h*64 + c] = O / l ----
#pragma unroll
    for (int i = 0; i < 8; i++) {
        int q = qt * BR + ty * 8 + i;
        float inv = 1.f / lrow[i];
        float4 o4 = make_float4(O[i][0] * inv, O[i][1] * inv,
                                O[i][2] * inv, O[i][3] * inv);
        *(float4*)&g_att[((size_t)b * NS + q) * NE + h * ND + tx * 4] = o4;
    }
}

// ============================================================
// LayerNorm over rows of g_Y (512 elems), 128 threads/row.
// ============================================================
__global__ __launch_bounds__(128) void ln_kernel(
    const float* __restrict__ ln_g, const float* __restrict__ ln_b,
    float* __restrict__ out)
{
    __shared__ float red[8];
    int row = blockIdx.x;
    int tid = threadIdx.x;
    const float* y = g_Y + (size_t)row * NE;
    float4 v = ((const float4*)y)[tid];
    float s = v.x + v.y + v.z + v.w;
    float s2 = v.x * v.x + v.y * v.y + v.z * v.z + v.w * v.w;
#pragma unroll
    for (int o = 16; o; o >>= 1) {
        s += __shfl_xor_sync(0xffffffffu, s, o);
        s2 += __shfl_xor_sync(0xffffffffu, s2, o);
    }
    int w = tid >> 5;
    if ((tid & 31) == 0) { red[w] = s; red[4 + w] = s2; }
    __syncthreads();
    s = red[0] + red[1] + red[2] + red[3];
    s2 = red[4] + red[5] + red[6] + red[7];
    float mu = s * (1.f / NE);
    float var = s2 * (1.f / NE) - mu * mu;
    float rstd = rsqrtf(var + 1e-5f);
    float4 g = ((const float4*)ln_g)[tid];
    float4 be = ((const float4*)ln_b)[tid];
    float4 o;
    o.x = (v.x - mu) * rstd * g.x + be.x;
    o.y = (v.y - mu) * rstd * g.y + be.y;
    o.z = (v.z - mu) * rstd * g.z + be.z;
    o.w = (v.w - mu) * rstd * g.w + be.w;
    ((float4*)(out + (size_t)row * NE))[tid] = o;
}

// ============================================================
extern "C" void kernel_launch(void* const* d_in, const int* in_sizes, int n_in,
                              void* d_out, int out_size)
{
    const float* x_p     = (const float*)d_in[0];
    const float* x_pcre  = (const float*)d_in[1];
    const float* bias    = (const float*)d_in[2];
    const int*   mask    = (const int*)d_in[3];   // bool -> int32 assumption
    const float* Wq      = (const float*)d_in[4];
    const float* Wkv     = (const float*)d_in[5];
    const float* Wff     = (const float*)d_in[6];
    const float* bff     = (const float*)d_in[7];
    const float* gamma_f = (const float*)d_in[8];
    const float* ln_g    = (const float*)d_in[9];
    const float* ln_b    = (const float*)d_in[10];
    float* out = (float*)d_out;

    const int MROWS = NB * NS;  // 16384

    // Q projection: (16384x512)@(512x512)
    sgemm_fused<<<dim3(512 / 128, MROWS / 128), 256>>>(x_p, Wq, nullptr, nullptr, 512, 0);
    // KV projection: (16384x512)@(512x1024)
    sgemm_fused<<<dim3(1024 / 128, MROWS / 128), 256>>>(x_pcre, Wkv, nullptr, nullptr, 1024, 1);

    // attention
    const int smem_att = (BR * LDP * 2 + BC * LDP * 2) * (int)sizeof(float) + BC * (int)sizeof(int);
    cudaFuncSetAttribute(attn_kernel, cudaFuncAttributeMaxDynamicSharedMemorySize, smem_att);
    attn_kernel<<<dim3(NS / BR, NH, NB), 256, smem_att>>>(bias, mask, gamma_f);

    // FF + bias + residual
    sgemm_fused<<<dim3(512 / 128, MROWS / 128), 256>>>(nullptr, Wff, bff, x_p, 512, 2);

    // LayerNorm
    ln_kernel<<<MROWS, 128>>>(ln_g, ln_b, out);
}

// round 5
// speedup vs baseline: 1.0043x; 1.0011x over previous
#include <cuda_runtime.h>
#include <math.h>
#include <stdint.h>

#define NB 8
#define NS 2048
#define NE 512
#define NH 8
#define ND 64

// ---- scratch (static device globals; no allocation) ----
__device__ float g_Q[(size_t)NB * NH * NS * ND];   // (b,h,s,d)
__device__ float g_K[(size_t)NB * NH * NS * ND];
__device__ float g_V[(size_t)NB * NH * NS * ND];
__device__ float g_att[(size_t)NB * NS * NE];      // (b*s, h*64+d)
__device__ float g_Y[(size_t)NB * NS * NE];

// ============================================================
// Fused SGEMM: 128x128x8 block tile, 8x8 per-thread microtile.
// mode 0: X=x_p,  W=Wq  (N=512)  -> scatter into g_Q (b,h,s,d)
// mode 1: X=x_pcre, W=Wkv (N=1024)-> scatter into g_K / g_V
// mode 2: X=g_att, W=Wff (N=512) -> + bff + resid -> g_Y
// ============================================================
__global__ __launch_bounds__(256) void sgemm_fused(
    const float* __restrict__ X, const float* __restrict__ W,
    const float* __restrict__ bff, const float* __restrict__ resid,
    int N, int mode)
{
    __shared__ float As[8][128];   // transposed A tile
    __shared__ float Bs[8][128];
    const int K = NE;
    const int tid = threadIdx.x;
    const int bn = blockIdx.x, bm = blockIdx.y;
    const int rowA = tid >> 1, colA = (tid & 1) << 2;
    const int rowB = tid >> 5, colB = (tid & 31) << 2;
    const int tr = tid >> 4, tc = tid & 15;

    const float* Xbase = (mode == 2) ? g_att : X;
    const float* Xp = Xbase + (size_t)bm * 128 * K;
    const float* Wp = W + (size_t)bn * 128;

    float acc[8][8];
#pragma unroll
    for (int i = 0; i < 8; i++)
#pragma unroll
        for (int j = 0; j < 8; j++) acc[i][j] = 0.f;

    for (int k0 = 0; k0 < K; k0 += 8) {
        float4 a = *(const float4*)(Xp + (size_t)rowA * K + k0 + colA);
        As[colA + 0][rowA] = a.x;
        As[colA + 1][rowA] = a.y;
        As[colA + 2][rowA] = a.z;
        As[colA + 3][rowA] = a.w;
        *(float4*)&Bs[rowB][colB] =
            *(const float4*)(Wp + (size_t)(k0 + rowB) * N + colB);
        __syncthreads();
#pragma unroll
        for (int kk = 0; kk < 8; kk++) {
            float4 a0 = *(const float4*)&As[kk][tr * 8];
            float4 a1 = *(const float4*)&As[kk][tr * 8 + 4];
            float4 b0 = *(const float4*)&Bs[kk][tc * 8];
            float4 b1 = *(const float4*)&Bs[kk][tc * 8 + 4];
            float ar[8] = {a0.x, a0.y, a0.z, a0.w, a1.x, a1.y, a1.z, a1.w};
            float br[8] = {b0.x, b0.y, b0.z, b0.w, b1.x, b1.y, b1.z, b1.w};
#pragma unroll
            for (int i = 0; i < 8; i++)
#pragma unroll
                for (int j = 0; j < 8; j++)
                    acc[i][j] = fmaf(ar[i], br[j], acc[i][j]);
        }
        __syncthreads();
    }

#pragma unroll
    for (int i = 0; i < 8; i++) {
        int m = bm * 128 + tr * 8 + i;
        int b = m >> 11;
        int s = m & (NS - 1);
#pragma unroll
        for (int j = 0; j < 8; j++) {
            int n = bn * 128 + tc * 8 + j;
            float v = acc[i][j];
            if (mode == 0) {
                int h = n >> 6, d = n & 63;
                g_Q[(((size_t)b * NH + h) * NS + s) * ND + d] = v;
            } else if (mode == 1) {
                int c2 = n >> 9;
                int h = (n >> 6) & 7, d = n & 63;
                float* dst = c2 ? g_V : g_K;
                dst[(((size_t)b * NH + h) * NS + s) * ND + d] = v;
            } else {
                g_Y[(size_t)m * NE + n] = v + bff[n] + resid[(size_t)m * NE + n];
            }
        }
    }
}

// ============================================================
// Flash attention: Br=128 q-rows, Bc=64 keys per iter, D=64.
// 256 threads: ty(0..15) owns 8 rows, tx(0..15) owns 4 cols.
// Online softmax; bias streamed from gmem; mask -> exact -1e9.
// ============================================================
#define BR 128
#define BC 64
#define LDP 68   // padded smem row stride (floats), 16B-aligned rows

__global__ __launch_bounds__(256) void attn_kernel(
    const float* __restrict__ bias, const int* __restrict__ mask,
    const float* __restrict__ gamma_f)
{
    extern __shared__ float sm[];
    float* Qs = sm;                    // BR x LDP
    float* Ks = Qs + BR * LDP;         // BC x LDP
    float* Vs = Ks + BC * LDP;         // BC x LDP
    float* Ps = Vs + BC * LDP;         // BR x LDP
    int* msk = (int*)(Ps + BR * LDP);  // BC ints

    const int qt = blockIdx.x, h = blockIdx.y, b = blockIdx.z;
    const int tid = threadIdx.x;
    const int ty = tid >> 4, tx = tid & 15;
    const size_t bh = (size_t)b * NH + h;
    const float* Qg = g_Q + (bh * NS + (size_t)qt * BR) * ND;
    const float* Kg = g_K + bh * NS * ND;
    const float* Vg = g_V + bh * NS * ND;
    const float gamma = gamma_f[h];
    const float* biasBase = bias + ((size_t)b * NS + (size_t)qt * BR) * NS;
    const int* maskBase = mask + (size_t)b * NS;

    // load Q tile
    for (int t = tid; t < BR * (ND / 4); t += 256) {
        int r = t >> 4, c4 = (t & 15) << 2;
        *(float4*)&Qs[r * LDP + c4] = *(const float4*)(Qg + r * ND + c4);
    }

    float mrow[8], lrow[8], O[8][4];
#pragma unroll
    for (int i = 0; i < 8; i++) {
        mrow[i] = -3.0e38f;
        lrow[i] = 0.f;
#pragma unroll
        for (int j = 0; j < 4; j++) O[i][j] = 0.f;
    }

    for (int kt = 0; kt < NS / BC; kt++) {
        __syncthreads();   // prev iteration fully done before overwriting K/V
        const float* Kt = Kg + (size_t)kt * BC * ND;
        const float* Vt = Vg + (size_t)kt * BC * ND;
        for (int t = tid; t < BC * (ND / 4); t += 256) {
            int r = t >> 4, c4 = (t & 15) << 2;
            *(float4*)&Ks[r * LDP + c4] = *(const float4*)(Kt + r * ND + c4);
            *(float4*)&Vs[r * LDP + c4] = *(const float4*)(Vt + r * ND + c4);
        }
        if (tid < BC) msk[tid] = maskBase[kt * BC + tid];
        __syncthreads();

        // ---- S = Q K^T (BR x BC), microtile 8x4 ----
        float acc[8][4];
#pragma unroll
        for (int i = 0; i < 8; i++)
#pragma unroll
            for (int j = 0; j < 4; j++) acc[i][j] = 0.f;

        for (int d0 = 0; d0 < ND; d0 += 4) {
            float4 q4[8], k4[4];
#pragma unroll
            for (int i = 0; i < 8; i++)
                q4[i] = *(const float4*)&Qs[(ty * 8 + i) * LDP + d0];
#pragma unroll
            for (int j = 0; j < 4; j++)
                k4[j] = *(const float4*)&Ks[(tx * 4 + j) * LDP + d0];
#pragma unroll
            for (int i = 0; i < 8; i++)
#pragma unroll
                for (int j = 0; j < 4; j++) {
                    acc[i][j] = fmaf(q4[i].x, k4[j].x, acc[i][j]);
                    acc[i][j] = fmaf(q4[i].y, k4[j].y, acc[i][j]);
                    acc[i][j] = fmaf(q4[i].z, k4[j].z, acc[i][j]);
                    acc[i][j] = fmaf(q4[i].w, k4[j].w, acc[i][j]);
                }
        }

        // ---- bias + mask + online softmax (row reduce over 16 lanes) ----
        int mk0 = msk[tx * 4 + 0], mk1 = msk[tx * 4 + 1];
        int mk2 = msk[tx * 4 + 2], mk3 = msk[tx * 4 + 3];
#pragma unroll
        for (int i = 0; i < 8; i++) {
            int r = ty * 8 + i;
            float4 b4 = *(const float4*)(biasBase + (size_t)r * NS + kt * BC + tx * 4);
            float sv[4];
            sv[0] = mk0 ? -1e9f : acc[i][0] * 0.125f + gamma * b4.x;
            sv[1] = mk1 ? -1e9f : acc[i][1] * 0.125f + gamma * b4.y;
            sv[2] = mk2 ? -1e9f : acc[i][2] * 0.125f + gamma * b4.z;
            sv[3] = mk3 ? -1e9f : acc[i][3] * 0.125f + gamma * b4.w;
            float mx = fmaxf(fmaxf(sv[0], sv[1]), fmaxf(sv[2], sv[3]));
#pragma unroll
            for (int o = 8; o; o >>= 1)
                mx = fmaxf(mx, __shfl_xor_sync(0xffffffffu, mx, o, 16));
            float mnew = fmaxf(mrow[i], mx);
            float corr = __expf(mrow[i] - mnew);
            float rs = 0.f;
#pragma unroll
            for (int j = 0; j < 4; j++) {
                sv[j] = __expf(sv[j] - mnew);
                rs += sv[j];
            }
#pragma unroll
            for (int o = 8; o; o >>= 1)
                rs += __shfl_xor_sync(0xffffffffu, rs, o, 16);
            lrow[i] = lrow[i] * corr + rs;
            mrow[i] = mnew;
#pragma unroll
            for (int j = 0; j < 4; j++) O[i][j] *= corr;
            *(float4*)&Ps[r * LDP + tx * 4] = make_float4(sv[0], sv[1], sv[2], sv[3]);
        }
        __syncthreads();

        // ---- O += P V (BR x 64), microtile 8 rows x 4 d-cols ----
        for (int k0 = 0; k0 < BC; k0 += 4) {
            float4 v0 = *(const float4*)&Vs[(k0 + 0) * LDP + tx * 4];
            float4 v1 = *(const float4*)&Vs[(k0 + 1) * LDP + tx * 4];
            float4 v2 = *(const float4*)&Vs[(k0 + 2) * LDP + tx * 4];
            float4 v3 = *(const float4*)&Vs[(k0 + 3) * LDP + tx * 4];
#pragma unroll
            for (int i = 0; i < 8; i++) {
                float4 p = *(const float4*)&Ps[(ty * 8 + i) * LDP + k0];
                O[i][0] += p.x * v0.x + p.y * v1.x + p.z * v2.x + p.w * v3.x;
                O[i][1] += p.x * v0.y + p.y * v1.y + p.z * v2.y + p.w * v3.y;
                O[i][2] += p.x * v0.z + p.y * v1.z + p.z * v2.z + p.w * v3.z;
                O[i][3] += p.x * v0.w + p.y * v1.w + p.z * v2.w + p.w * v3.w;
            }
        }
    }

    // ---- epilogue: att[(b*S+q)*512 + h*64 + c] = O / l ----
#pragma unroll
    for (int i = 0; i < 8; i++) {
        int q = qt * BR + ty * 8 + i;
        float inv = 1.f / lrow[i];
        float4 o4 = make_float4(O[i][0] * inv, O[i][1] * inv,
                                O[i][2] * inv, O[i][3] * inv);
        *(float4*)&g_att[((size_t)b * NS + q) * NE + h * ND + tx * 4] = o4;
    }
}

// ============================================================
// LayerNorm over rows of g_Y (512 elems), 128 threads/row.
// ============================================================
__global__ __launch_bounds__(128) void ln_kernel(
    const float* __restrict__ ln_g, const float* __restrict__ ln_b,
    float* __restrict__ out)
{
    __shared__ float red[8];
    int row = blockIdx.x;
    int tid = threadIdx.x;
    const float* y = g_Y + (size_t)row * NE;
    float4 v = ((const float4*)y)[tid];
    float s = v.x + v.y + v.z + v.w;
    float s2 = v.x * v.x + v.y * v.y + v.z * v.z + v.w * v.w;
#pragma unroll
    for (int o = 16; o; o >>= 1) {
        s += __shfl_xor_sync(0xffffffffu, s, o);
        s2 += __shfl_xor_sync(0xffffffffu, s2, o);
    }
    int w = tid >> 5;
    if ((tid & 31) == 0) { red[w] = s; red[4 + w] = s2; }
    __syncthreads();
    s = red[0] + red[1] + red[2] + red[3];
    s2 = red[4] + red[5] + red[6] + red[7];
    float mu = s * (1.f / NE);
    float var = s2 * (1.f / NE) - mu * mu;
    float rstd = rsqrtf(var + 1e-5f);
    float4 g = ((const float4*)ln_g)[tid];
    float4 be = ((const float4*)ln_b)[tid];
    float4 o;
    o.x = (v.x - mu) * rstd * g.x + be.x;
    o.y = (v.y - mu) * rstd * g.y + be.y;
    o.z = (v.z - mu) * rstd * g.z + be.z;
    o.w = (v.w - mu) * rstd * g.w + be.w;
    ((float4*)(out + (size_t)row * NE))[tid] = o;
}

// ============================================================
extern "C" void kernel_launch(void* const* d_in, const int* in_sizes, int n_in,
                              void* d_out, int out_size)
{
    const float* x_p     = (const float*)d_in[0];
    const float* x_pcre  = (const float*)d_in[1];
    const float* bias    = (const float*)d_in[2];
    const int*   mask    = (const int*)d_in[3];   // bool -> int32 assumption
    const float* Wq      = (const float*)d_in[4];
    const float* Wkv     = (const float*)d_in[5];
    const float* Wff     = (const float*)d_in[6];
    const float* bff     = (const float*)d_in[7];
    const float* gamma_f = (const float*)d_in[8];
    const float* ln_g    = (const float*)d_in[9];
    const float* ln_b    = (const float*)d_in[10];
    float* out = (float*)d_out;

    const int MROWS = NB * NS;  // 16384

    // Q projection: (16384x512)@(512x512)
    sgemm_fused<<<dim3(512 / 128, MROWS / 128), 256>>>(x_p, Wq, nullptr, nullptr, 512, 0);
    // KV projection: (16384x512)@(512x1024)
    sgemm_fused<<<dim3(1024 / 128, MROWS / 128), 256>>>(x_pcre, Wkv, nullptr, nullptr, 1024, 1);

    // attention
    const int smem_att = (BR * LDP * 2 + BC * LDP * 2) * (int)sizeof(float) + BC * (int)sizeof(int);
    cudaFuncSetAttribute(attn_kernel, cudaFuncAttributeMaxDynamicSharedMemorySize, smem_att);
    attn_kernel<<<dim3(NS / BR, NH, NB), 256, smem_att>>>(bias, mask, gamma_f);

    // FF + bias + residual
    sgemm_fused<<<dim3(512 / 128, MROWS / 128), 256>>>(nullptr, Wff, bff, x_p, 512, 2);

    // LayerNorm
    ln_kernel<<<MROWS, 128>>>(ln_g, ln_b, out);
}